// round 4
// baseline (speedup 1.0000x reference)
#include <cuda_runtime.h>
#include <math_constants.h>

#define IW 224
#define IH 224
#define CCH 32

// Load the 8-float window [xbase-2, xbase+6) of input row `ry` into R[0..7].
// One aligned LDG.128 + 4 shuffles; lanes 0/31 patch halos with predicated loads.
// Out-of-bounds (rows or cols) -> -inf (tropical neutral).
__device__ __forceinline__ void load_row8(float (&R)[8], const float* __restrict__ x,
                                          int ry, int xbase) {
    const float NEG = -CUDART_INF_F;
    bool rv = ((unsigned)ry < (unsigned)IH);
    const float* row = x + ry * IW;
    float4 c;
    if (rv && (xbase < IW)) {
        c = *(const float4*)(row + xbase);
    } else {
        c.x = NEG; c.y = NEG; c.z = NEG; c.w = NEG;
    }
    float lz = __shfl_up_sync(0xffffffffu, c.z, 1);
    float lw = __shfl_up_sync(0xffffffffu, c.w, 1);
    float rx = __shfl_down_sync(0xffffffffu, c.x, 1);
    float ryv = __shfl_down_sync(0xffffffffu, c.y, 1);
    int lane = threadIdx.x & 31;
    if (lane == 0) {
        int c0 = xbase - 2;           // -2 for tile 0, 126 for tile 1
        lz = (rv && c0 >= 0) ? row[c0] : NEG;
        lw = (rv && c0 + 1 >= 0) ? row[c0 + 1] : NEG;
    }
    if (lane == 31) {
        int c0 = xbase + 4;           // 128 for tile 0, 256 for tile 1
        rx = (rv && c0 < IW) ? row[c0] : NEG;
        ryv = (rv && c0 + 1 < IW) ? row[c0 + 1] : NEG;
    }
    R[0] = lz; R[1] = lw; R[2] = c.x; R[3] = c.y;
    R[4] = c.z; R[5] = c.w; R[6] = rx; R[7] = ryv;
}

// out[b,c,y,x] = max_{i,j in [0,5)} x[b,c,y+i-2,x+j-2] + kernel[c,0,4-i,4-j]
__global__ void __launch_bounds__(128, 5)
tropical_conv2d_kernel(const float* __restrict__ x,
                       const float* __restrict__ kw,
                       float* __restrict__ out) {
    const float NEG = -CUDART_INF_F;
    int bx = blockIdx.x;
    int tile = bx & 1;          // x-tile: cols [0,128) or [128,224)
    int yq   = (bx >> 1) & 1;   // y-half: rows [0,112) or [112,224)
    int img  = bx >> 2;         // b*C + c
    int lane = threadIdx.x & 31;
    int warp = threadIdx.x >> 5;
    int xbase = tile * 128 + lane * 4;
    bool do_store = (xbase < IW);

    const float* xi = x + (size_t)img * (IH * IW);
    float* oi = out + (size_t)img * (IH * IW);
    int c = img & (CCH - 1);
    const float* kc = kw + c * 25;

    // wt[i*5+j] = kernel[c,0,4-i,4-j] = kc[24 - (i*5+j)]
    float wt[25];
#pragma unroll
    for (int t = 0; t < 25; ++t) wt[t] = __ldg(kc + (24 - t));

    int y0 = yq * 112 + warp * 28;   // 2 y-halves x 4 warps x 28 rows = 224
    float R[5][8];
#pragma unroll
    for (int r = 0; r < 5; ++r) load_row8(R[r], xi, y0 - 2 + r, xbase);

    float* orow = oi + y0 * IW + xbase;
#pragma unroll 7
    for (int s = 0; s < 28; ++s) {
        float a0 = NEG, a1 = NEG, a2 = NEG, a3 = NEG;
#pragma unroll
        for (int i = 0; i < 5; ++i) {
#pragma unroll
            for (int j = 0; j < 5; ++j) {
                float wv = wt[i * 5 + j];
                a0 = fmaxf(a0, R[i][j] + wv);
                a1 = fmaxf(a1, R[i][j + 1] + wv);
                a2 = fmaxf(a2, R[i][j + 2] + wv);
                a3 = fmaxf(a3, R[i][j + 3] + wv);
            }
        }
        if (do_store) {
            *(float4*)orow = make_float4(a0, a1, a2, a3);
        }
        orow += IW;
        // slide window down one row (copies vanish under unroll via renaming)
#pragma unroll
        for (int r = 0; r < 4; ++r)
#pragma unroll
            for (int k = 0; k < 8; ++k) R[r][k] = R[r + 1][k];
        load_row8(R[4], xi, y0 + s + 3, xbase);
    }
}

extern "C" void kernel_launch(void* const* d_in, const int* in_sizes, int n_in,
                              void* d_out, int out_size) {
    const float* x = (const float*)d_in[0];   // (8,32,224,224) fp32
    const float* k = (const float*)d_in[1];   // (32,1,5,5) fp32
    float* out = (float*)d_out;               // (8,32,224,224) fp32
    // 256 images x 2 x-tiles x 2 y-halves; 128 threads = 4 warps x 28-row strips
    tropical_conv2d_kernel<<<1024, 128>>>(x, k, out);
}

// round 6
// speedup vs baseline: 1.5770x; 1.5770x over previous
#include <cuda_runtime.h>
#include <math_constants.h>

#define IW 224
#define IH 224
#define CCH 32
#define TROWS 32      // 28 output rows + 4 halo
#define TCOLS 132     // 128 output cols + 4 halo
#define TSTRIDE 136   // padded to 16B multiple

// out[b,c,y,x] = max_{i,j} x[b,c,y+i-2,x+j-2] + kernel[c,0,4-i,4-j], oob -> -inf
__global__ void __launch_bounds__(128, 8)
tropical_conv2d_kernel(const float* __restrict__ x,
                       const float* __restrict__ kw,
                       float* __restrict__ out) {
    __shared__ float tile[TROWS][TSTRIDE];
    const float NEG = -CUDART_INF_F;

    int bx   = blockIdx.x;
    int xt   = (bx & 1) * 128;      // x-tile base col (0 or 128)
    int band = (bx >> 1) & 7;       // y-band 0..7 (28 rows each)
    int img  = bx >> 4;             // b*C + c
    int tid  = threadIdx.x;
    int lane = tid & 31;
    int warp = tid >> 5;
    int y0   = band * 28;

    const float* xi = x + (size_t)img * (IH * IW);
    float* oi = out + (size_t)img * (IH * IW);
    const float* kc = kw + (img & (CCH - 1)) * 25;

    // wt[i*5+j] = kernel[c,0,4-i,4-j] = kc[24 - (5i+j)]
    float wt[25];
#pragma unroll
    for (int t = 0; t < 25; ++t) wt[t] = __ldg(kc + (24 - t));

    // ---- stage input tile (rows y0-2..y0+29, cols xt-2..xt+129), -inf borders ----
    {
        // phase A: col = tid (0..127)
        int gcA = xt - 2 + tid;
        bool cvA = ((unsigned)gcA < IW);
#pragma unroll 8
        for (int r = 0; r < TROWS; ++r) {
            int gr = y0 - 2 + r;
            bool v = cvA && ((unsigned)gr < IH);
            float val = NEG;
            if (v) val = xi[gr * IW + gcA];
            tile[r][tid] = val;
        }
        // phase B: cols 128..131, 32 rows x 4 cols by 128 threads in one shot
        int r2 = tid >> 2;
        int c2 = 128 + (tid & 3);
        int gr2 = y0 - 2 + r2;
        int gc2 = xt - 2 + c2;
        bool v2 = ((unsigned)gr2 < IH) && ((unsigned)gc2 < IW);
        float val2 = NEG;
        if (v2) val2 = xi[gr2 * IW + gc2];
        tile[r2][c2] = val2;
    }
    __syncthreads();

    // ---- compute: warp w owns output rows y0+7w .. y0+7w+6; lane owns 4 cols ----
    int x0 = xt + lane * 4;
    bool do_store = (x0 < IW);
    int rbase = warp * 7;                 // local row of first output (tile row rbase..rbase+4 window)
    float* op = oi + (size_t)(y0 + rbase) * IW + x0;

#pragma unroll
    for (int s = 0; s < 7; ++s) {
        float a0 = NEG, a1 = NEG, a2 = NEG, a3 = NEG;
#pragma unroll
        for (int i = 0; i < 5; ++i) {
            const float* trow = &tile[rbase + s + i][lane * 4];
            float4 L = *(const float4*)(trow);      // cols x0-2 .. x0+1
            float4 H = *(const float4*)(trow + 4);  // cols x0+2 .. x0+5
            float W[8] = {L.x, L.y, L.z, L.w, H.x, H.y, H.z, H.w};
#pragma unroll
            for (int j = 0; j < 5; ++j) {
                float wv = wt[i * 5 + j];
                a0 = fmaxf(a0, W[j]     + wv);
                a1 = fmaxf(a1, W[j + 1] + wv);
                a2 = fmaxf(a2, W[j + 2] + wv);
                a3 = fmaxf(a3, W[j + 3] + wv);
            }
        }
        if (do_store) {
            *(float4*)op = make_float4(a0, a1, a2, a3);
        }
        op += IW;
    }
}

extern "C" void kernel_launch(void* const* d_in, const int* in_sizes, int n_in,
                              void* d_out, int out_size) {
    const float* x = (const float*)d_in[0];   // (8,32,224,224) fp32
    const float* k = (const float*)d_in[1];   // (32,1,5,5) fp32
    float* out = (float*)d_out;               // (8,32,224,224) fp32
    // 256 images x 2 x-tiles x 8 y-bands = 4096 blocks; 128 thr = 4 warps x 7 rows
    tropical_conv2d_kernel<<<4096, 128>>>(x, k, out);
}

// round 10
// speedup vs baseline: 1.9064x; 1.2089x over previous
#include <cuda_runtime.h>
#include <math_constants.h>

#define IW 224
#define IH 224
#define CCH 32
#define RB 28          // output rows per block
#define TROWS 32       // RB + 4 halo
#define TSTRIDE 232    // 228 cols (224 + 4 halo) padded

// out[b,c,y,x] = max_{i,j} x[b,c,y+i-2,x+j-2] + kernel[c,0,4-i,4-j], oob -> -inf
// tile[r][c]: global row y0-2+r, global col c-2. Cols 0,1,226,227 always -inf.
__global__ void __launch_bounds__(224, 4)
tropical_conv2d_kernel(const float* __restrict__ x,
                       const float* __restrict__ kw,
                       float* __restrict__ out) {
    __shared__ float tile[TROWS][TSTRIDE];
    const float NEG = -CUDART_INF_F;

    int bx   = blockIdx.x;
    int band = bx & 7;              // 0..7, 8 bands x 28 rows = 224
    int img  = bx >> 3;             // b*C + c, 0..255
    int tid  = threadIdx.x;
    int u    = tid % 56;            // col-quad: owns cols 4u..4u+3
    int g    = tid / 56;            // row-group 0..3
    int y0   = band * RB;

    const float* xi = x + (size_t)img * (IH * IW);
    float* oi = out + (size_t)img * (IH * IW);
    const float* kc = kw + (img & (CCH - 1)) * 25;

    // wt[i*5+j] = kernel[c,0,4-i,4-j] = kc[24 - (5i+j)]
    float wt[25];
#pragma unroll
    for (int t = 0; t < 25; ++t) wt[t] = __ldg(kc + (24 - t));

    // ---- x-halo cols (always outside image): 32 rows x 4 cols -> -inf ----
    if (tid < 128) {
        int r = tid >> 2;
        int c = tid & 3;
        c = (c < 2) ? c : (c + 224);   // cols 0,1,226,227
        tile[r][c] = NEG;
    }

    // ---- stage bulk: 32 rows x 56 quads; thread (g,u) does rows g,g+4,...,g+28 ----
#pragma unroll
    for (int k = 0; k < 8; ++k) {
        int r = g + 4 * k;
        int gr = y0 - 2 + r;
        float4 v;
        if ((unsigned)gr < (unsigned)IH) {
            v = *(const float4*)(xi + gr * IW + 4 * u);
        } else {
            v.x = NEG; v.y = NEG; v.z = NEG; v.w = NEG;
        }
        // tile col 4u+2 is 8-byte aligned -> two 64-bit stores
        float2* d = (float2*)&tile[r][4 * u + 2];
        d[0] = make_float2(v.x, v.y);
        d[1] = make_float2(v.z, v.w);
    }
    __syncthreads();

    // ---- compute: thread (g,u) -> output rows y0+7g+s (s<7), cols 4u..4u+3 ----
    int x0 = 4 * u;
    int rbase = 7 * g;
    float* op = oi + (size_t)(y0 + rbase) * IW + x0;

#pragma unroll
    for (int s = 0; s < 7; ++s) {
        float a0 = NEG, a1 = NEG, a2 = NEG, a3 = NEG;
#pragma unroll
        for (int i = 0; i < 5; ++i) {
            const float* trow = &tile[rbase + s + i][x0];
            float4 L = *(const float4*)(trow);      // tile cols x0..x0+3  (global x0-2..x0+1)
            float4 H = *(const float4*)(trow + 4);  // tile cols x0+4..x0+7
            float W[8] = {L.x, L.y, L.z, L.w, H.x, H.y, H.z, H.w};
#pragma unroll
            for (int j = 0; j < 5; ++j) {
                float wv = wt[i * 5 + j];
                a0 = fmaxf(a0, W[j]     + wv);
                a1 = fmaxf(a1, W[j + 1] + wv);
                a2 = fmaxf(a2, W[j + 2] + wv);
                a3 = fmaxf(a3, W[j + 3] + wv);
            }
        }
        *(float4*)op = make_float4(a0, a1, a2, a3);
        op += IW;
    }
}

extern "C" void kernel_launch(void* const* d_in, const int* in_sizes, int n_in,
                              void* d_out, int out_size) {
    const float* x = (const float*)d_in[0];   // (8,32,224,224) fp32
    const float* k = (const float*)d_in[1];   // (32,1,5,5) fp32
    float* out = (float*)d_out;               // (8,32,224,224) fp32
    // 256 images x 8 y-bands = 2048 blocks; 224 thr = 4 row-groups x 56 col-quads
    tropical_conv2d_kernel<<<2048, 224>>>(x, k, out);
}